// round 1
// baseline (speedup 1.0000x reference)
#include <cuda_runtime.h>

// Problem constants
#define BQ    4
#define CCH   2
#define SLEN  4096
#define KW    64
#define NKF   32
#define OUTC  512
#define TDIM  72        // padded t-range; valid t = 0..64
#define KSPLIT 8
#define QCHUNK 512      // K elements per split-K block
#define XSLEN  1096     // 2*511 + 71 + 1 = 1094, padded
#define WSROW  65       // ws row stride (conflict-free: 65 mod 32 = 1)

// Scratch (device globals: no allocations allowed)
__device__ float g_Tpart[KSPLIT * BQ * OUTC * TDIM];   // 4.7 MB partials
__device__ float g_Tred[BQ * OUTC * TDIM];

// ---- packed f32x2 helpers (sm_100+ PTX; 2x FFMA throughput vs 3-reg FFMA) ----
__device__ __forceinline__ unsigned long long pack2(float a, float b) {
    unsigned long long r;
    asm("mov.b64 %0, {%1, %2};" : "=l"(r) : "f"(a), "f"(b));
    return r;
}
__device__ __forceinline__ void ffma2(unsigned long long& d, unsigned long long a, unsigned long long b) {
    asm("fma.rn.f32x2 %0, %1, %2, %0;" : "+l"(d) : "l"(a), "l"(b));
}
__device__ __forceinline__ float2 unpack2(unsigned long long v) {
    float2 r;
    asm("mov.b64 {%0, %1}, %2;" : "=f"(r.x), "=f"(r.y) : "l"(v));
    return r;
}

// ============================================================================
// Kernel A: partial strided-correlation GEMM
//   Tpart[kc][b][o][t] = sum over this block's K-chunk of
//       conv_w[o, c*2048+u] * xpad[b, c, 2u+t]
// Block: 144 threads = 16 o-rows x 9 t-columns. Each thread: 4 o's x 8 t's
// (4 f32x2 accumulator pairs per o). x window rolls by one pair per q step.
// Grid: (8 o-tiles, 4 batch, 8 k-chunks)
// ============================================================================
__global__ __launch_bounds__(144)
void gemm_partial_kernel(const float* __restrict__ x,
                         const float* __restrict__ conv_w) {
    __shared__ __align__(16) float xs[XSLEN];
    __shared__ float ws[64 * WSROW];

    const int otile = blockIdx.x;   // 0..7  -> 64 o's each
    const int b     = blockIdx.y;   // 0..3
    const int kc    = blockIdx.z;   // 0..7  -> 512 K each

    const int tid = threadIdx.x;
    const int k0  = kc * QCHUNK;
    const int ci  = k0 >> 11;       // channel for this chunk
    const int qq0 = k0 & 2047;      // q offset within channel
    const int obase = otile * 64;

    // Stage x slice: xs[j] = xpad[b, ci, 2*qq0 + j]
    const float* xrow = x + (b * CCH + ci) * SLEN;
    for (int i = tid; i < XSLEN; i += 144) {
        int g = 2 * qq0 + i;
        xs[i] = (g < SLEN) ? xrow[g] : 0.0f;
    }
    __syncthreads();

    const int row = tid / 9;        // 0..15
    const int col = tid - row * 9;  // 0..8
    const int t0  = col * 8;        // 0,8,...,64

    // rolling x window: 4 packed pairs covering xs[t0 .. t0+7] at q=0
    unsigned long long P0 = *(const unsigned long long*)&xs[t0 + 0];
    unsigned long long P1 = *(const unsigned long long*)&xs[t0 + 2];
    unsigned long long P2 = *(const unsigned long long*)&xs[t0 + 4];
    unsigned long long P3 = *(const unsigned long long*)&xs[t0 + 6];

    unsigned long long acc[4][4];
    #pragma unroll
    for (int j = 0; j < 4; j++)
        #pragma unroll
        for (int p = 0; p < 4; p++)
            acc[j][p] = 0ull;  // packed (0.0f, 0.0f)

    const float* wbase = conv_w + (size_t)obase * 4096 + k0;
    const int wrow = row * 4;

    for (int kk0 = 0; kk0 < QCHUNK; kk0 += 64) {
        __syncthreads();  // previous compute done reading ws
        for (int i = tid; i < 64 * 64; i += 144) {
            int ol = i >> 6, kx = i & 63;
            ws[ol * WSROW + kx] = wbase[(size_t)ol * 4096 + (kk0 + kx)];
        }
        __syncthreads();

        #pragma unroll 8
        for (int kk = 0; kk < 64; kk++) {
            const int ql = kk0 + kk;
            float w0 = ws[(wrow + 0) * WSROW + kk];
            float w1 = ws[(wrow + 1) * WSROW + kk];
            float w2 = ws[(wrow + 2) * WSROW + kk];
            float w3 = ws[(wrow + 3) * WSROW + kk];
            unsigned long long wp0 = pack2(w0, w0);
            unsigned long long wp1 = pack2(w1, w1);
            unsigned long long wp2 = pack2(w2, w2);
            unsigned long long wp3 = pack2(w3, w3);

            ffma2(acc[0][0], wp0, P0); ffma2(acc[0][1], wp0, P1);
            ffma2(acc[0][2], wp0, P2); ffma2(acc[0][3], wp0, P3);
            ffma2(acc[1][0], wp1, P0); ffma2(acc[1][1], wp1, P1);
            ffma2(acc[1][2], wp1, P2); ffma2(acc[1][3], wp1, P3);
            ffma2(acc[2][0], wp2, P0); ffma2(acc[2][1], wp2, P1);
            ffma2(acc[2][2], wp2, P2); ffma2(acc[2][3], wp2, P3);
            ffma2(acc[3][0], wp3, P0); ffma2(acc[3][1], wp3, P1);
            ffma2(acc[3][2], wp3, P2); ffma2(acc[3][3], wp3, P3);

            // shift window by 2 (one pair): load xs[2*(ql+1)+t0+6 .. +7]
            unsigned long long Pn = *(const unsigned long long*)&xs[2 * ql + t0 + 8];
            P0 = P1; P1 = P2; P2 = P3; P3 = Pn;
        }
    }

    // write partials: Tpart[kc][b][o][t]
    float* tp = g_Tpart + ((size_t)(kc * BQ + b) * OUTC) * TDIM;
    #pragma unroll
    for (int j = 0; j < 4; j++) {
        float* dst = tp + (size_t)(obase + wrow + j) * TDIM + t0;
        #pragma unroll
        for (int p = 0; p < 4; p++) {
            float2 v = unpack2(acc[j][p]);
            dst[2 * p]     = v.x;
            dst[2 * p + 1] = v.y;
        }
    }
}

// ============================================================================
// Kernel B: split-K reduction (tiny)
// ============================================================================
__global__ __launch_bounds__(256)
void reduce_kernel() {
    int i = blockIdx.x * 256 + threadIdx.x;   // grid sized exactly
    float s = 0.0f;
    #pragma unroll
    for (int ks = 0; ks < KSPLIT; ks++)
        s += g_Tpart[(size_t)ks * (BQ * OUTC * TDIM) + i];
    g_Tred[i] = s;
}

// ============================================================================
// Kernel C: epilogue
//   out[b,o, p*2048 + m*32 + l] = relu( stft_w[l,m] * T[b,o,p+m] + conv_b[o] )
// Block per (b,o): 256 threads, 4 float4 stores each (coalesced STG.128).
// ============================================================================
__global__ __launch_bounds__(256)
void epilogue_kernel(const float* __restrict__ stft_w,
                     const float* __restrict__ conv_b,
                     float* __restrict__ out) {
    __shared__ __align__(16) float swT[2048];   // transposed: swT[m*32 + l]
    __shared__ float Ts[TDIM];

    const int bo  = blockIdx.x;       // b*512 + o
    const int o   = bo & 511;
    const int tid = threadIdx.x;

    for (int i = tid; i < 2048; i += 256) {
        int l = i >> 6, m = i & 63;
        swT[m * 32 + l] = stft_w[i];
    }
    if (tid < TDIM)
        Ts[tid] = g_Tred[(size_t)bo * TDIM + tid];
    const float bias = conv_b[o];
    __syncthreads();

    float4* out4 = (float4*)(out + (size_t)bo * 4096);
    #pragma unroll
    for (int it = 0; it < 4; it++) {
        int q  = tid + it * 256;      // quad index; s' = 4*q
        int sp = q * 4;
        int p  = sp >> 11;
        int m  = (sp >> 5) & 63;
        int l0 = sp & 31;             // multiple of 4
        float tv = Ts[p + m];
        float4 sw = *(const float4*)&swT[m * 32 + l0];
        float4 r;
        r.x = fmaxf(fmaf(sw.x, tv, bias), 0.0f);
        r.y = fmaxf(fmaf(sw.y, tv, bias), 0.0f);
        r.z = fmaxf(fmaf(sw.z, tv, bias), 0.0f);
        r.w = fmaxf(fmaf(sw.w, tv, bias), 0.0f);
        out4[q] = r;
    }
}

// ============================================================================
extern "C" void kernel_launch(void* const* d_in, const int* in_sizes, int n_in,
                              void* d_out, int out_size) {
    const float* x      = nullptr;
    const float* stft_w = nullptr;
    const float* conv_w = nullptr;
    const float* conv_b = nullptr;
    for (int i = 0; i < n_in; i++) {
        switch (in_sizes[i]) {
            case BQ * CCH * SLEN:  x      = (const float*)d_in[i]; break;  // 32768
            case NKF * KW:         stft_w = (const float*)d_in[i]; break;  // 2048
            case OUTC * 4096:      conv_w = (const float*)d_in[i]; break;  // 2097152
            case OUTC:             conv_b = (const float*)d_in[i]; break;  // 512
        }
    }

    gemm_partial_kernel<<<dim3(8, BQ, KSPLIT), 144>>>(x, conv_w);
    reduce_kernel<<<(BQ * OUTC * TDIM) / 256, 256>>>();
    epilogue_kernel<<<BQ * OUTC, 256>>>(stft_w, conv_b, (float*)d_out);
}